// round 9
// baseline (speedup 1.0000x reference)
#include <cuda_runtime.h>
#include <cuda_fp16.h>
#include <math.h>

#define D      1024
#define PD     32
#define NPAT   256
#define TOPK   4
#define THREADS 256

#define TBL_N  (NPAT * D * PD)   // 8,388,608 elements per table

// fp16 copies of the weight tables (allocation-free __device__ scratch)
struct alignas(16) H8 { __half2 a, b, c, d; };
struct alignas(8)  H4 { __half2 a, b; };

__device__ H8 g_vd_h[TBL_N / 8];   // [NPAT][D][PD] as half, 16 MB
__device__ H8 g_vu_h[TBL_N / 8];   // [NPAT][PD][D] as half, 16 MB

// ---------------- prologue: fp32 -> fp16 table conversion ----------------
__global__ __launch_bounds__(256) void convert_kernel(
    const float4* __restrict__ src, H8* __restrict__ dst)
{
    const int i = blockIdx.x * blockDim.x + threadIdx.x;   // one H8 (8 floats)
    const float4 a = src[2 * i];
    const float4 b = src[2 * i + 1];
    H8 o;
    o.a = __floats2half2_rn(a.x, a.y);
    o.b = __floats2half2_rn(a.z, a.w);
    o.c = __floats2half2_rn(b.x, b.y);
    o.d = __floats2half2_rn(b.z, b.w);
    dst[i] = o;
}

// ---------------- fused per-token kernel ----------------
__global__ __launch_bounds__(THREADS) void peer_fused_kernel(
    const float* __restrict__ x,
    const float* __restrict__ hw,      // [PD, D] fp32 (routing stays exact)
    const float* __restrict__ keys,    // [NPAT, PD]
    const float* __restrict__ scale,   // [1]
    float* __restrict__ out)
{
    __shared__ float xs[D];
    __shared__ float hs[PD];
    __shared__ float sims[NPAT];
    __shared__ float partial[8 * 32];   // [warp][j]
    __shared__ float proj[PD];
    __shared__ float wk_s[TOPK];
    __shared__ int   idx_s[TOPK];
    __shared__ float kval_s[TOPK];
    __shared__ float scale_s;

    const int tok  = blockIdx.x;
    const int tid  = threadIdx.x;
    const int lane = tid & 31;
    const int w    = tid >> 5;

    // ---- stage x (coalesced float4) ----
    const float4* xg4 = reinterpret_cast<const float4*>(x + (size_t)tok * D);
    float4 xv4 = xg4[tid];
    reinterpret_cast<float4*>(xs)[tid] = xv4;
    if (tid == 0) scale_s = scale[0];
    __syncthreads();

    // ---- hash: h[j] = dot(hw[j], x); warp w owns j = 4w..4w+3 ----
    {
        const float4* hw4 = reinterpret_cast<const float4*>(hw);
        const float4* xs4 = reinterpret_cast<const float4*>(xs);
        #pragma unroll
        for (int jj = 0; jj < 4; jj++) {
            const int j = w * 4 + jj;
            float acc = 0.f;
            #pragma unroll
            for (int i = 0; i < 8; i++) {
                float4 a = hw4[j * (D / 4) + lane + 32 * i];
                float4 b = xs4[lane + 32 * i];
                acc += a.x * b.x + a.y * b.y + a.z * b.z + a.w * b.w;
            }
            #pragma unroll
            for (int off = 16; off; off >>= 1)
                acc += __shfl_xor_sync(0xFFFFFFFFu, acc, off);
            if (lane == 0) hs[j] = acc;
        }
    }
    __syncthreads();

    // ---- sim[n] = dot(keys[n], h): one pattern per thread ----
    {
        const float4* k4 = reinterpret_cast<const float4*>(keys + tid * PD);
        const float4* h4 = reinterpret_cast<const float4*>(hs);
        float s = 0.f;
        #pragma unroll
        for (int i = 0; i < 8; i++) {
            float4 a = k4[i]; float4 b = h4[i];
            s += a.x * b.x + a.y * b.y + a.z * b.z + a.w * b.w;
        }
        sims[tid] = s;
    }
    __syncthreads();

    // ---- top-4 (warp 0), ties -> lower index ----
    if (w == 0) {
        for (int k = 0; k < TOPK; k++) {
            float bv = -1e30f; int bi = 0;
            #pragma unroll
            for (int t = 0; t < 8; t++) {
                const int n = lane * 8 + t;
                const float v = sims[n];
                if (v > bv) { bv = v; bi = n; }
            }
            #pragma unroll
            for (int off = 16; off; off >>= 1) {
                const float ov = __shfl_xor_sync(0xFFFFFFFFu, bv, off);
                const int   oi = __shfl_xor_sync(0xFFFFFFFFu, bi, off);
                if (ov > bv || (ov == bv && oi < bi)) { bv = ov; bi = oi; }
            }
            if (lane == 0) { idx_s[k] = bi; kval_s[k] = bv; sims[bi] = -1e30f; }
            __syncwarp();
        }
        if (lane == 0) {
            const float m = kval_s[0];
            float e[TOPK]; float ssum = 0.f;
            #pragma unroll
            for (int k = 0; k < TOPK; k++) { e[k] = expf(kval_s[k] - m); ssum += e[k]; }
            const float sc = scale_s / ssum;
            #pragma unroll
            for (int k = 0; k < TOPK; k++) wk_s[k] = e[k] * sc;
        }
    }
    __syncthreads();

    // ---- expert loop on fp16 tables ----
    // down mapping: lane -> (c = int4 within 64B row: 8 j's, dsub = 8 d's)
    // each warp request = 8 rows x 64B = 512B fully coalesced.
    const int c    = lane & 3;
    const int dsub = lane >> 2;

    float2 o0 = make_float2(0.f, 0.f), o1 = make_float2(0.f, 0.f);

    for (int k = 0; k < TOPK; k++) {
        const int p = idx_s[k];
        const H8* vd8 = g_vd_h + (size_t)p * (D * PD / 8);

        float2 a0 = make_float2(0.f, 0.f), a1 = a0, a2 = a0, a3 = a0;
        const int dbase = w * 128 + dsub;
        #pragma unroll
        for (int i = 0; i < 16; i++) {
            const int d = dbase + i * 8;
            const float xv = xs[d];
            const H8 r = vd8[d * 4 + c];
            const float2 f0 = __half22float2(r.a);
            const float2 f1 = __half22float2(r.b);
            const float2 f2 = __half22float2(r.c);
            const float2 f3 = __half22float2(r.d);
            a0.x += xv * f0.x; a0.y += xv * f0.y;
            a1.x += xv * f1.x; a1.y += xv * f1.y;
            a2.x += xv * f2.x; a2.y += xv * f2.y;
            a3.x += xv * f3.x; a3.y += xv * f3.y;
        }
        // reduce over dsub (xor 4, 8, 16)
        #pragma unroll
        for (int off = 4; off < 32; off <<= 1) {
            a0.x += __shfl_xor_sync(0xFFFFFFFFu, a0.x, off);
            a0.y += __shfl_xor_sync(0xFFFFFFFFu, a0.y, off);
            a1.x += __shfl_xor_sync(0xFFFFFFFFu, a1.x, off);
            a1.y += __shfl_xor_sync(0xFFFFFFFFu, a1.y, off);
            a2.x += __shfl_xor_sync(0xFFFFFFFFu, a2.x, off);
            a2.y += __shfl_xor_sync(0xFFFFFFFFu, a2.y, off);
            a3.x += __shfl_xor_sync(0xFFFFFFFFu, a3.x, off);
            a3.y += __shfl_xor_sync(0xFFFFFFFFu, a3.y, off);
        }
        if (dsub == 0) {
            float* pw = partial + w * 32 + c * 8;
            pw[0] = a0.x; pw[1] = a0.y; pw[2] = a1.x; pw[3] = a1.y;
            pw[4] = a2.x; pw[5] = a2.y; pw[6] = a3.x; pw[7] = a3.y;
        }
        __syncthreads();

        if (tid < PD) {
            float s = 0.f;
            #pragma unroll
            for (int ww = 0; ww < 8; ww++) s += partial[ww * 32 + tid];
            const float sig = 1.f / (1.f + expf(-s));
            proj[tid] = s * sig * wk_s[k];       // silu(s) * w_k * scale
        }
        __syncthreads();

        // up: thread owns d = 4*tid..4*tid+3 (one H4 = 8B per j-row; 2KB/warp-request)
        const H4* vu4 = reinterpret_cast<const H4*>(g_vu_h) + (size_t)p * (PD * D / 4);
        #pragma unroll 8
        for (int j = 0; j < PD; j++) {
            const float pj = proj[j];            // smem broadcast
            const H4 r = vu4[j * (D / 4) + tid];
            const float2 f0 = __half22float2(r.a);
            const float2 f1 = __half22float2(r.b);
            o0.x += pj * f0.x; o0.y += pj * f0.y;
            o1.x += pj * f1.x; o1.y += pj * f1.y;
        }
        // no trailing sync needed: proj rewrite is gated by the post-partial
        // __syncthreads (see R4 argument).
    }

    float4 res;
    res.x = xv4.x + o0.x; res.y = xv4.y + o0.y;
    res.z = xv4.z + o1.x; res.w = xv4.w + o1.y;
    reinterpret_cast<float4*>(out)[(size_t)tok * (D / 4) + tid] = res;
}

// ---------------- launcher ----------------
extern "C" void kernel_launch(void* const* d_in, const int* in_sizes, int n_in,
                              void* d_out, int out_size) {
    const float* x     = (const float*)d_in[0];
    const float* hw    = (const float*)d_in[1];
    const float* keys  = (const float*)d_in[2];
    const float* vd    = (const float*)d_in[3];
    const float* vu    = (const float*)d_in[4];
    const float* scale = (const float*)d_in[5];
    float* out = (float*)d_out;

    const int ntok = in_sizes[0] / D;   // 2048

    const int n8 = TBL_N / 8;           // 1,048,576 H8 per table
    convert_kernel<<<n8 / 256, 256>>>((const float4*)vd, g_vd_h);
    convert_kernel<<<n8 / 256, 256>>>((const float4*)vu, g_vu_h);
    peer_fused_kernel<<<ntok, THREADS>>>(x, hw, keys, scale, out);
}

// round 10
// speedup vs baseline: 1.9642x; 1.9642x over previous
#include <cuda_runtime.h>
#include <cuda_fp16.h>
#include <math.h>

#define D      1024
#define PD     32
#define NPAT   256
#define TOPK   4
#define THREADS 256

#define TBL_N  (NPAT * D * PD)   // 8,388,608 elements per table

// fp16 copies of the weight tables (allocation-free __device__ scratch)
struct alignas(16) H8 { __half2 a, b, c, d; };
struct alignas(8)  H4 { __half2 a, b; };

__device__ H8 g_vd_h[TBL_N / 8];   // [NPAT][D][PD] as half, 16 MB
__device__ H8 g_vu_h[TBL_N / 8];   // [NPAT][PD][D] as half, 16 MB

// ---------------- prologue: fp32 -> fp16 table conversion ----------------
// One float4 (16B) load -> one uint2 (8B) store per thread. Both sides
// perfectly coalesced (warp: 512B read, 256B write, zero gaps).
// __ldcs: stream the fp32 source through L2 without evicting the hot set.
__global__ __launch_bounds__(256) void convert_kernel(
    const float4* __restrict__ src, uint2* __restrict__ dst)
{
    const int i = blockIdx.x * blockDim.x + threadIdx.x;   // one float4
    const float4 v = __ldcs(&src[i]);
    __half2 h0 = __floats2half2_rn(v.x, v.y);
    __half2 h1 = __floats2half2_rn(v.z, v.w);
    uint2 o;
    o.x = *reinterpret_cast<unsigned int*>(&h0);
    o.y = *reinterpret_cast<unsigned int*>(&h1);
    dst[i] = o;
}

// ---------------- fused per-token kernel ----------------
__global__ __launch_bounds__(THREADS) void peer_fused_kernel(
    const float* __restrict__ x,
    const float* __restrict__ hw,      // [PD, D] fp32 (routing stays exact)
    const float* __restrict__ keys,    // [NPAT, PD]
    const float* __restrict__ scale,   // [1]
    float* __restrict__ out)
{
    __shared__ float xs[D];
    __shared__ float hs[PD];
    __shared__ float sims[NPAT];
    __shared__ float partial[8 * 32];   // [warp][j]
    __shared__ float proj[PD];
    __shared__ float wk_s[TOPK];
    __shared__ int   idx_s[TOPK];
    __shared__ float kval_s[TOPK];
    __shared__ float scale_s;

    const int tok  = blockIdx.x;
    const int tid  = threadIdx.x;
    const int lane = tid & 31;
    const int w    = tid >> 5;

    // ---- stage x (coalesced float4) ----
    const float4* xg4 = reinterpret_cast<const float4*>(x + (size_t)tok * D);
    float4 xv4 = xg4[tid];
    reinterpret_cast<float4*>(xs)[tid] = xv4;
    if (tid == 0) scale_s = scale[0];
    __syncthreads();

    // ---- hash: h[j] = dot(hw[j], x); warp w owns j = 4w..4w+3 ----
    {
        const float4* hw4 = reinterpret_cast<const float4*>(hw);
        const float4* xs4 = reinterpret_cast<const float4*>(xs);
        #pragma unroll
        for (int jj = 0; jj < 4; jj++) {
            const int j = w * 4 + jj;
            float acc = 0.f;
            #pragma unroll
            for (int i = 0; i < 8; i++) {
                float4 a = hw4[j * (D / 4) + lane + 32 * i];
                float4 b = xs4[lane + 32 * i];
                acc += a.x * b.x + a.y * b.y + a.z * b.z + a.w * b.w;
            }
            #pragma unroll
            for (int off = 16; off; off >>= 1)
                acc += __shfl_xor_sync(0xFFFFFFFFu, acc, off);
            if (lane == 0) hs[j] = acc;
        }
    }
    __syncthreads();

    // ---- sim[n] = dot(keys[n], h): one pattern per thread ----
    {
        const float4* k4 = reinterpret_cast<const float4*>(keys + tid * PD);
        const float4* h4 = reinterpret_cast<const float4*>(hs);
        float s = 0.f;
        #pragma unroll
        for (int i = 0; i < 8; i++) {
            float4 a = k4[i]; float4 b = h4[i];
            s += a.x * b.x + a.y * b.y + a.z * b.z + a.w * b.w;
        }
        sims[tid] = s;
    }
    __syncthreads();

    // ---- top-4 (warp 0), ties -> lower index ----
    if (w == 0) {
        for (int k = 0; k < TOPK; k++) {
            float bv = -1e30f; int bi = 0;
            #pragma unroll
            for (int t = 0; t < 8; t++) {
                const int n = lane * 8 + t;
                const float v = sims[n];
                if (v > bv) { bv = v; bi = n; }
            }
            #pragma unroll
            for (int off = 16; off; off >>= 1) {
                const float ov = __shfl_xor_sync(0xFFFFFFFFu, bv, off);
                const int   oi = __shfl_xor_sync(0xFFFFFFFFu, bi, off);
                if (ov > bv || (ov == bv && oi < bi)) { bv = ov; bi = oi; }
            }
            if (lane == 0) { idx_s[k] = bi; kval_s[k] = bv; sims[bi] = -1e30f; }
            __syncwarp();
        }
        if (lane == 0) {
            const float m = kval_s[0];
            float e[TOPK]; float ssum = 0.f;
            #pragma unroll
            for (int k = 0; k < TOPK; k++) { e[k] = expf(kval_s[k] - m); ssum += e[k]; }
            const float sc = scale_s / ssum;
            #pragma unroll
            for (int k = 0; k < TOPK; k++) wk_s[k] = e[k] * sc;
        }
    }
    __syncthreads();

    // ---- expert loop on fp16 tables ----
    // down mapping: lane -> (c = int4 within 64B row: 8 j's, dsub = 8 d's)
    // each warp request = 8 rows x 64B = 512B fully coalesced.
    const int c    = lane & 3;
    const int dsub = lane >> 2;

    float2 o0 = make_float2(0.f, 0.f), o1 = make_float2(0.f, 0.f);

    for (int k = 0; k < TOPK; k++) {
        const int p = idx_s[k];
        const H8* vd8 = g_vd_h + (size_t)p * (D * PD / 8);

        float2 a0 = make_float2(0.f, 0.f), a1 = a0, a2 = a0, a3 = a0;
        const int dbase = w * 128 + dsub;
        #pragma unroll
        for (int i = 0; i < 16; i++) {
            const int d = dbase + i * 8;
            const float xv = xs[d];
            const H8 r = vd8[d * 4 + c];
            const float2 f0 = __half22float2(r.a);
            const float2 f1 = __half22float2(r.b);
            const float2 f2 = __half22float2(r.c);
            const float2 f3 = __half22float2(r.d);
            a0.x += xv * f0.x; a0.y += xv * f0.y;
            a1.x += xv * f1.x; a1.y += xv * f1.y;
            a2.x += xv * f2.x; a2.y += xv * f2.y;
            a3.x += xv * f3.x; a3.y += xv * f3.y;
        }
        // reduce over dsub (xor 4, 8, 16)
        #pragma unroll
        for (int off = 4; off < 32; off <<= 1) {
            a0.x += __shfl_xor_sync(0xFFFFFFFFu, a0.x, off);
            a0.y += __shfl_xor_sync(0xFFFFFFFFu, a0.y, off);
            a1.x += __shfl_xor_sync(0xFFFFFFFFu, a1.x, off);
            a1.y += __shfl_xor_sync(0xFFFFFFFFu, a1.y, off);
            a2.x += __shfl_xor_sync(0xFFFFFFFFu, a2.x, off);
            a2.y += __shfl_xor_sync(0xFFFFFFFFu, a2.y, off);
            a3.x += __shfl_xor_sync(0xFFFFFFFFu, a3.x, off);
            a3.y += __shfl_xor_sync(0xFFFFFFFFu, a3.y, off);
        }
        if (dsub == 0) {
            float* pw = partial + w * 32 + c * 8;
            pw[0] = a0.x; pw[1] = a0.y; pw[2] = a1.x; pw[3] = a1.y;
            pw[4] = a2.x; pw[5] = a2.y; pw[6] = a3.x; pw[7] = a3.y;
        }
        __syncthreads();

        if (tid < PD) {
            float s = 0.f;
            #pragma unroll
            for (int ww = 0; ww < 8; ww++) s += partial[ww * 32 + tid];
            const float sig = 1.f / (1.f + expf(-s));
            proj[tid] = s * sig * wk_s[k];       // silu(s) * w_k * scale
        }
        __syncthreads();

        // up: thread owns d = 4*tid..4*tid+3 (one H4 = 8B per j-row)
        const H4* vu4 = reinterpret_cast<const H4*>(g_vu_h) + (size_t)p * (PD * D / 4);
        #pragma unroll 8
        for (int j = 0; j < PD; j++) {
            const float pj = proj[j];            // smem broadcast
            const H4 r = vu4[j * (D / 4) + tid];
            const float2 f0 = __half22float2(r.a);
            const float2 f1 = __half22float2(r.b);
            o0.x += pj * f0.x; o0.y += pj * f0.y;
            o1.x += pj * f1.x; o1.y += pj * f1.y;
        }
        // no trailing sync needed: proj rewrite is gated by the post-partial
        // __syncthreads (see R4 argument).
    }

    float4 res;
    res.x = xv4.x + o0.x; res.y = xv4.y + o0.y;
    res.z = xv4.z + o1.x; res.w = xv4.w + o1.y;
    reinterpret_cast<float4*>(out)[(size_t)tok * (D / 4) + tid] = res;
}

// ---------------- launcher ----------------
extern "C" void kernel_launch(void* const* d_in, const int* in_sizes, int n_in,
                              void* d_out, int out_size) {
    const float* x     = (const float*)d_in[0];
    const float* hw    = (const float*)d_in[1];
    const float* keys  = (const float*)d_in[2];
    const float* vd    = (const float*)d_in[3];
    const float* vu    = (const float*)d_in[4];
    const float* scale = (const float*)d_in[5];
    float* out = (float*)d_out;

    const int ntok = in_sizes[0] / D;   // 2048

    const int n4 = TBL_N / 4;           // 2,097,152 float4 per table
    convert_kernel<<<n4 / 256, 256>>>((const float4*)vd, (uint2*)g_vd_h);
    convert_kernel<<<n4 / 256, 256>>>((const float4*)vu, (uint2*)g_vu_h);
    peer_fused_kernel<<<ntok, THREADS>>>(x, hw, keys, scale, out);
}